// round 1
// baseline (speedup 1.0000x reference)
#include <cuda_runtime.h>
#include <cuda_bf16.h>

#define NB      4
#define TT      32
#define DW      300
#define HD      128     // per-direction hidden
#define G3      384     // 3*HD
#define HID     256     // DIM_HIDDEN
#define GDIM    64
#define DESCL   16
#define NNODES  20000
#define NEDGES  320000
#define NCLASS  2000
#define DP      68      // padded desc row in smem

// ---------------- scratch (device globals; no allocation allowed) ----------
__device__ float g_gx[2 * NB * TT * G3];       // precomputed input gates
__device__ float g_qemb[NB * HID];
__device__ float g_qg[NB * GDIM];
__device__ float g_nf[NNODES * NB * GDIM];     // node feats pre-RGCN [N][B][G]
__device__ float g_agg[NNODES * NB * GDIM];    // scatter result
__device__ float g_nf2[NNODES * NB * GDIM];    // post-RGCN
__device__ int   g_counts[NNODES + 1];
__device__ int   g_offsets[NNODES + 1];
__device__ int   g_cursor[NNODES];
__device__ int   g_ssrc[NEDGES];
__device__ float g_sw[NEDGES];
__device__ float g_s2[NB * NNODES];            // pooling scores -> probs
__device__ float g_mx[NB];
__device__ float g_sumz[NB];
__device__ float g_nagg[NB * GDIM];
__device__ float g_hidden[NB * 1024];

__device__ __forceinline__ float sigmoidf_(float x) { return 1.f / (1.f + __expf(-x)); }

// ---------------- zero counts ------------------------------------------------
__global__ void k_zero() {
    int i = blockIdx.x * blockDim.x + threadIdx.x;
    if (i < NNODES + 1) g_counts[i] = 0;
}

// ---------------- gx = x @ Wx + bx  (both directions) ------------------------
// grid 32 = dir(2) x b(4) x tq(4, 8 timesteps each), 384 threads
__global__ void k_gx(const int* __restrict__ q, const float* __restrict__ emb_word,
                     const float* __restrict__ Wx_f, const float* __restrict__ bx_f,
                     const float* __restrict__ Wx_b, const float* __restrict__ bx_b) {
    int bid = blockIdx.x;
    int dir = bid >> 4, b = (bid >> 2) & 3, tq = bid & 3;
    const float* Wx = dir ? Wx_b : Wx_f;
    const float* bx = dir ? bx_b : bx_f;
    __shared__ float xs[8 * DW];
    int tid = threadIdx.x;
    for (int i = tid; i < 8 * DW; i += 384) {
        int t = i / DW, k = i % DW;
        int tok = q[b * TT + tq * 8 + t];
        xs[i] = emb_word[(long)tok * DW + k];
    }
    __syncthreads();
    float acc[8];
    float bj = bx[tid];
#pragma unroll
    for (int t = 0; t < 8; t++) acc[t] = bj;
    for (int k = 0; k < DW; k++) {
        float w = Wx[k * G3 + tid];
#pragma unroll
        for (int t = 0; t < 8; t++) acc[t] += xs[t * DW + k] * w;
    }
#pragma unroll
    for (int t = 0; t < 8; t++)
        g_gx[((dir * NB + b) * TT + tq * 8 + t) * G3 + tid] = acc[t];
}

// ---------------- GRU recurrence: 8 blocks = (dir, b), Wh in dyn smem --------
__global__ void k_gru(const float* __restrict__ Wh_f, const float* __restrict__ bh_f,
                      const float* __restrict__ Wh_b, const float* __restrict__ bh_b,
                      const int* __restrict__ q) {
    extern __shared__ float Wh_s[];      // 128*384 floats = 192KB
    __shared__ float h_s[HD];
    __shared__ float gh_s[G3];
    int bid = blockIdx.x;
    int dir = bid >> 2, b = bid & 3;
    const float* Wh = dir ? Wh_b : Wh_f;
    const float* bh = dir ? bh_b : bh_f;
    int tid = threadIdx.x;               // 384
    for (int i = tid; i < HD * G3; i += G3) Wh_s[i] = Wh[i];
    if (tid < HD) h_s[tid] = 0.f;
    float bhj = bh[tid];
    __syncthreads();
    for (int step = 0; step < TT; step++) {
        int t = dir ? (TT - 1 - step) : step;
        float acc = bhj;
#pragma unroll 8
        for (int k = 0; k < HD; k++) acc += h_s[k] * Wh_s[k * G3 + tid];
        gh_s[tid] = acc;
        __syncthreads();
        if (tid < HD) {
            const float* gxp = &g_gx[((dir * NB + b) * TT + t) * G3];
            float r  = sigmoidf_(gxp[tid]          + gh_s[tid]);
            float z  = sigmoidf_(gxp[tid + HD]     + gh_s[tid + HD]);
            float nn = tanhf(gxp[tid + 2 * HD] + r * gh_s[tid + 2 * HD]);
            float hold = h_s[tid];
            float hnew = (1.f - z) * nn + z * hold;
            bool  m = (q[b * TT + t] != 0);
            h_s[tid] = m ? hnew : hold;
        }
        __syncthreads();
    }
    if (tid < HD) g_qemb[b * HID + dir * HD + tid] = h_s[tid];
}

// ---------------- q_g = q_emb @ W_hg + b_hg ----------------------------------
__global__ void k_qg(const float* __restrict__ W_hg, const float* __restrict__ b_hg) {
    __shared__ float qe[NB * HID];
    int tid = threadIdx.x;               // 256
    for (int i = tid; i < NB * HID; i += 256) qe[i] = g_qemb[i];
    __syncthreads();
    int b = tid >> 6, g = tid & 63;
    float acc = b_hg[g];
    for (int k = 0; k < HID; k++) acc += qe[b * HID + k] * W_hg[k * GDIM + g];
    g_qg[tid] = acc;
}

// ---------------- attention over descriptions -> node features ---------------
__global__ void k_nodefeat(const int* __restrict__ node_descs,
                           const float* __restrict__ emb_desc) {
    __shared__ float ds[DESCL * DP];
    __shared__ float qgs[NB * GDIM];
    __shared__ float sc[NB * DESCL];
    __shared__ float at[NB * DESCL];
    int n = blockIdx.x;
    int tid = threadIdx.x;               // 256
    qgs[tid] = g_qg[tid];
    {
        int l = tid >> 4, r = tid & 15;
        int idx = node_descs[n * DESCL + l];
        float4 v = ((const float4*)emb_desc)[(long)idx * (GDIM / 4) + r];
        ds[l * DP + r * 4 + 0] = v.x;
        ds[l * DP + r * 4 + 1] = v.y;
        ds[l * DP + r * 4 + 2] = v.z;
        ds[l * DP + r * 4 + 3] = v.w;
    }
    __syncthreads();
    if (tid < NB * DESCL) {
        int b = tid >> 4, l = tid & 15;
        float s = 0.f;
#pragma unroll 8
        for (int g = 0; g < GDIM; g++) s += ds[l * DP + g] * qgs[b * GDIM + g];
        sc[tid] = s;
    }
    __syncthreads();
    if (tid < NB) {
        float m = -1e30f;
        for (int l = 0; l < DESCL; l++) m = fmaxf(m, sc[tid * DESCL + l]);
        float su = 0.f;
        for (int l = 0; l < DESCL; l++) { float e = __expf(sc[tid * DESCL + l] - m); at[tid * DESCL + l] = e; su += e; }
        float inv = 1.f / su;
        for (int l = 0; l < DESCL; l++) at[tid * DESCL + l] *= inv;
    }
    __syncthreads();
    int b = tid >> 6, g = tid & 63;
    float o = 0.f;
#pragma unroll
    for (int l = 0; l < DESCL; l++) o += at[b * DESCL + l] * ds[l * DP + g];
    g_nf[n * (NB * GDIM) + tid] = o;
}

// ---------------- CSR build: histogram, scan, bucket -------------------------
__global__ void k_hist(const int* __restrict__ edst) {
    int i = blockIdx.x * blockDim.x + threadIdx.x;
    if (i < NEDGES) atomicAdd(&g_counts[edst[i]], 1);
}

__global__ void k_scan() {
    __shared__ int wsum[32];
    __shared__ int carry_s;
    int tid = threadIdx.x, lane = tid & 31, wid = tid >> 5;
    if (tid == 0) carry_s = 0;
    __syncthreads();
    int nchunk = (NNODES + 1023) / 1024;
    for (int c = 0; c < nchunk; c++) {
        int i = c * 1024 + tid;
        int v = (i < NNODES) ? g_counts[i] : 0;
        int x = v;
#pragma unroll
        for (int o = 1; o < 32; o <<= 1) { int y = __shfl_up_sync(~0u, x, o); if (lane >= o) x += y; }
        if (lane == 31) wsum[wid] = x;
        __syncthreads();
        if (wid == 0) {
            int s = wsum[lane];
#pragma unroll
            for (int o = 1; o < 32; o <<= 1) { int y = __shfl_up_sync(~0u, s, o); if (lane >= o) s += y; }
            wsum[lane] = s;
        }
        __syncthreads();
        int incl = x + (wid > 0 ? wsum[wid - 1] : 0);
        int total = wsum[31];
        int base = carry_s;
        if (i < NNODES) { int e = base + incl - v; g_offsets[i] = e; g_cursor[i] = e; }
        __syncthreads();
        if (tid == 0) carry_s = base + total;
        __syncthreads();
    }
    if (tid == 0) g_offsets[NNODES] = carry_s;
}

__global__ void k_bucket(const int* __restrict__ esrc, const int* __restrict__ edst,
                         const int* __restrict__ etype, const float* __restrict__ w_comp) {
    int i = blockIdx.x * blockDim.x + threadIdx.x;
    if (i < NEDGES) {
        int d = edst[i];
        int pos = atomicAdd(&g_cursor[d], 1);
        g_ssrc[pos] = esrc[i];
        g_sw[pos]   = w_comp[etype[i]];
    }
}

// ---------------- RGCN aggregate: gather by destination ----------------------
__global__ void k_gather() {
    int n = blockIdx.x;
    int t = threadIdx.x;                 // 64 threads, float4 each => 256 floats
    int beg = g_offsets[n], end = g_offsets[n + 1];
    const float4* nf4 = (const float4*)g_nf;
    float4 a = make_float4(0.f, 0.f, 0.f, 0.f);
    int k = beg;
    for (; k + 1 < end; k += 2) {
        int   s0 = g_ssrc[k],   s1 = g_ssrc[k + 1];
        float w0 = g_sw[k],     w1 = g_sw[k + 1];
        float4 v0 = nf4[(long)s0 * 64 + t];
        float4 v1 = nf4[(long)s1 * 64 + t];
        a.x += w0 * v0.x + w1 * v1.x;
        a.y += w0 * v0.y + w1 * v1.y;
        a.z += w0 * v0.z + w1 * v1.z;
        a.w += w0 * v0.w + w1 * v1.w;
    }
    if (k < end) {
        int s0 = g_ssrc[k]; float w0 = g_sw[k];
        float4 v0 = nf4[(long)s0 * 64 + t];
        a.x += w0 * v0.x; a.y += w0 * v0.y; a.z += w0 * v0.z; a.w += w0 * v0.w;
    }
    ((float4*)g_agg)[(long)n * 64 + t] = a;
}

// ---------------- apply basis B0 + bias + relu -------------------------------
__global__ void k_transform(const float* __restrict__ bases, const float* __restrict__ rgcn_bias) {
    __shared__ float B0[GDIM * GDIM];
    __shared__ float ar[4 * GDIM];
    int tid = threadIdx.x;               // 256
    for (int i = tid; i < GDIM * GDIM; i += 256) B0[i] = bases[i];
    float bg = rgcn_bias[tid & 63];
    __syncthreads();
    const int rows = NNODES * NB;        // 80000
    for (int r0 = blockIdx.x * 4; r0 < rows; r0 += gridDim.x * 4) {
        int rr = r0 + (tid >> 6);
        ar[tid] = g_agg[(long)rr * GDIM + (tid & 63)];
        __syncthreads();
        int lr = tid >> 6, g = tid & 63;
        float acc = bg;
#pragma unroll 8
        for (int kk = 0; kk < GDIM; kk++) acc += ar[lr * GDIM + kk] * B0[kk * GDIM + g];
        g_nf2[(long)rr * GDIM + g] = fmaxf(acc, 0.f);
        __syncthreads();
    }
}

// ---------------- pooling: scores, softmax stats, probs, weighted sum --------
__global__ void k_score2() {
    int gw = blockIdx.x * 8 + (threadIdx.x >> 5);  // 80000 warps
    int lane = threadIdx.x & 31;
    if (gw < NNODES * NB) {
        int n = gw >> 2, b = gw & 3;
        const float* p = &g_nf2[(long)n * 256 + b * 64];
        float s = p[lane] * g_qg[b * 64 + lane] + p[lane + 32] * g_qg[b * 64 + lane + 32];
#pragma unroll
        for (int o = 16; o > 0; o >>= 1) s += __shfl_down_sync(~0u, s, o);
        if (lane == 0) g_s2[b * NNODES + n] = s;
    }
}

__global__ void k_redmax() {
    __shared__ float sh[1024];
    int b = blockIdx.x, tid = threadIdx.x;
    float m = -1e30f;
    for (int n = tid; n < NNODES; n += 1024) m = fmaxf(m, g_s2[b * NNODES + n]);
    sh[tid] = m; __syncthreads();
    for (int o = 512; o > 0; o >>= 1) { if (tid < o) sh[tid] = fmaxf(sh[tid], sh[tid + o]); __syncthreads(); }
    float mx = sh[0]; __syncthreads();
    float su = 0.f;
    for (int n = tid; n < NNODES; n += 1024) su += __expf(g_s2[b * NNODES + n] - mx);
    sh[tid] = su; __syncthreads();
    for (int o = 512; o > 0; o >>= 1) { if (tid < o) sh[tid] += sh[tid + o]; __syncthreads(); }
    if (tid == 0) { g_mx[b] = mx; g_sumz[b] = sh[0]; }
    if (tid < GDIM) g_nagg[b * GDIM + tid] = 0.f;
}

__global__ void k_prob() {
    int i = blockIdx.x * blockDim.x + threadIdx.x;
    if (i < NB * NNODES) {
        int b = i / NNODES;
        g_s2[i] = __expf(g_s2[i] - g_mx[b]) * (1.f / g_sumz[b]);
    }
}

__global__ void k_pool() {
    __shared__ float sh[4][64];
    int b = blockIdx.x >> 5, c = blockIdx.x & 31;
    int tid = threadIdx.x, g = tid & 63, r = tid >> 6;
    int n0 = c * 625, n1 = n0 + 625;
    float acc = 0.f;
    for (int n = n0 + r; n < n1; n += 4) {
        float p = g_s2[b * NNODES + n];
        acc += p * g_nf2[(long)n * 256 + b * 64 + g];
    }
    sh[r][g] = acc;
    __syncthreads();
    if (tid < 64) {
        float tot = sh[0][tid] + sh[1][tid] + sh[2][tid] + sh[3][tid];
        atomicAdd(&g_nagg[b * 64 + tid], tot);
    }
}

// ---------------- classifier -------------------------------------------------
__global__ void k_fc1(const float* __restrict__ W1, const float* __restrict__ b1) {
    __shared__ float fs[NB * 320];
    int tid = threadIdx.x;               // 256
    for (int i = tid; i < NB * 320; i += 256) {
        int b = i / 320, kk = i % 320;
        fs[i] = (kk < 64) ? g_nagg[b * 64 + kk] : g_qemb[b * 256 + (kk - 64)];
    }
    __syncthreads();
    int o = blockIdx.x * 256 + tid;      // 4096
    int b = o >> 10, j = o & 1023;
    float acc = b1[j];
#pragma unroll 4
    for (int kk = 0; kk < 320; kk++) acc += fs[b * 320 + kk] * W1[kk * 1024 + j];
    g_hidden[o] = fmaxf(acc, 0.f);
}

__global__ void k_fc2(const float* __restrict__ W2, const float* __restrict__ b2,
                      float* __restrict__ out) {
    __shared__ float hs[NB * 1024];
    int tid = threadIdx.x;               // 256
    for (int i = tid; i < NB * 1024; i += 256) hs[i] = g_hidden[i];
    __syncthreads();
    int o = blockIdx.x * 256 + tid;
    if (o < NB * NCLASS) {
        int b = o / NCLASS, j = o % NCLASS;
        float acc = b2[j];
#pragma unroll 4
        for (int kk = 0; kk < 1024; kk++) acc += hs[b * 1024 + kk] * W2[kk * NCLASS + j];
        out[o] = acc;
    }
}

// ---------------- launch -----------------------------------------------------
extern "C" void kernel_launch(void* const* d_in, const int* in_sizes, int n_in,
                              void* d_out, int out_size) {
    const int*   questions  = (const int*)  d_in[0];
    const int*   node_descs = (const int*)  d_in[1];
    const int*   edge_src   = (const int*)  d_in[2];
    const int*   edge_dst   = (const int*)  d_in[3];
    const int*   edge_type  = (const int*)  d_in[4];
    const float* emb_word   = (const float*)d_in[5];
    const float* emb_desc   = (const float*)d_in[6];
    const float* Wx_f       = (const float*)d_in[7];
    const float* Wh_f       = (const float*)d_in[8];
    const float* bx_f       = (const float*)d_in[9];
    const float* bh_f       = (const float*)d_in[10];
    const float* Wx_b       = (const float*)d_in[11];
    const float* Wh_b       = (const float*)d_in[12];
    const float* bx_b       = (const float*)d_in[13];
    const float* bh_b       = (const float*)d_in[14];
    const float* W_hg       = (const float*)d_in[15];
    const float* b_hg       = (const float*)d_in[16];
    const float* bases      = (const float*)d_in[17];
    const float* w_comp     = (const float*)d_in[18];
    const float* rgcn_bias  = (const float*)d_in[19];
    const float* W1         = (const float*)d_in[20];
    const float* b1         = (const float*)d_in[21];
    const float* W2         = (const float*)d_in[22];
    const float* b2         = (const float*)d_in[23];
    float* out = (float*)d_out;

    cudaFuncSetAttribute(k_gru, cudaFuncAttributeMaxDynamicSharedMemorySize, HD * G3 * 4);

    k_zero<<<(NNODES + 256) / 256, 256>>>();
    k_gx<<<32, 384>>>(questions, emb_word, Wx_f, bx_f, Wx_b, bx_b);
    k_gru<<<8, 384, HD * G3 * 4>>>(Wh_f, bh_f, Wh_b, bh_b, questions);
    k_qg<<<1, 256>>>(W_hg, b_hg);
    k_nodefeat<<<NNODES, 256>>>(node_descs, emb_desc);
    k_hist<<<(NEDGES + 255) / 256, 256>>>(edge_dst);
    k_scan<<<1, 1024>>>();
    k_bucket<<<(NEDGES + 255) / 256, 256>>>(edge_src, edge_dst, edge_type, w_comp);
    k_gather<<<NNODES, 64>>>();
    k_transform<<<500, 256>>>(bases, rgcn_bias);
    k_score2<<<NNODES * NB / 8, 256>>>();
    k_redmax<<<NB, 1024>>>();
    k_prob<<<(NB * NNODES + 1023) / 1024, 1024>>>();
    k_pool<<<NB * 32, 256>>>();
    k_fc1<<<16, 256>>>(W1, b1);
    k_fc2<<<(NB * NCLASS + 255) / 256, 256>>>(W2, b2, out);
}

// round 2
// speedup vs baseline: 1.5285x; 1.5285x over previous
#include <cuda_runtime.h>
#include <cuda_bf16.h>

#define NB      4
#define TT      32
#define DW      300
#define HD      128     // per-direction hidden
#define G3      384     // 3*HD
#define HID     256     // DIM_HIDDEN
#define GDIM    64
#define DESCL   16
#define NNODES  20000
#define NEDGES  320000
#define NCLASS  2000
#define DP      68      // padded desc row in smem

// ---------------- scratch (device globals; no allocation allowed) ----------
__device__ float g_gx[2 * NB * TT * G3];       // precomputed input gates
__device__ float g_qemb[NB * HID];
__device__ float g_qg[NB * GDIM];
__device__ float g_nf[NNODES * NB * GDIM];     // node feats pre-RGCN [N][B][G]
__device__ float g_nf2[NNODES * NB * GDIM];    // post-RGCN
__device__ int   g_counts[NNODES + 1];
__device__ int   g_offsets[NNODES + 1];
__device__ int   g_cursor[NNODES];
__device__ int   g_ssrc[NEDGES];
__device__ float g_sw[NEDGES];
__device__ float g_s2[NB * NNODES];            // pooling scores
__device__ float g_mx[NB];
__device__ float g_sumz[NB];
__device__ float g_nagg[NB * GDIM];
__device__ float g_hidden[NB * 1024];

__device__ __forceinline__ float sigmoidf_(float x) { return 1.f / (1.f + __expf(-x)); }

// ---------------- zero counts + qg accumulator -------------------------------
__global__ void k_zero() {
    int i = blockIdx.x * blockDim.x + threadIdx.x;
    if (i < NNODES + 1) g_counts[i] = 0;
    if (i < NB * GDIM) g_qg[i] = 0.f;
}

// ---------------- gx = x @ Wx + bx  (both directions) ------------------------
__global__ void k_gx(const int* __restrict__ q, const float* __restrict__ emb_word,
                     const float* __restrict__ Wx_f, const float* __restrict__ bx_f,
                     const float* __restrict__ Wx_b, const float* __restrict__ bx_b) {
    int bid = blockIdx.x;
    int dir = bid >> 4, b = (bid >> 2) & 3, tq = bid & 3;
    const float* Wx = dir ? Wx_b : Wx_f;
    const float* bx = dir ? bx_b : bx_f;
    __shared__ float xs[8 * DW];
    int tid = threadIdx.x;
    for (int i = tid; i < 8 * DW; i += 384) {
        int t = i / DW, k = i % DW;
        int tok = q[b * TT + tq * 8 + t];
        xs[i] = emb_word[(long)tok * DW + k];
    }
    __syncthreads();
    float acc[8];
    float bj = bx[tid];
#pragma unroll
    for (int t = 0; t < 8; t++) acc[t] = bj;
    for (int k = 0; k < DW; k++) {
        float w = Wx[k * G3 + tid];
#pragma unroll
        for (int t = 0; t < 8; t++) acc[t] += xs[t * DW + k] * w;
    }
#pragma unroll
    for (int t = 0; t < 8; t++)
        g_gx[((dir * NB + b) * TT + tq * 8 + t) * G3 + tid] = acc[t];
}

// ---------------- GRU recurrence: Wh register-resident -----------------------
// 8 blocks = (dir, b). Thread tid holds Wh[:, tid] in 128 registers; h is
// broadcast from smem via float4 (crossbar cost 16B/step/warp instead of
// re-reading 192KB of Wh through the 128B/cyc crossbar every step).
__global__ void __launch_bounds__(384, 1)
k_gru(const float* __restrict__ Wh_f, const float* __restrict__ bh_f,
      const float* __restrict__ Wh_b, const float* __restrict__ bh_b,
      const int* __restrict__ q) {
    __shared__ float4 h4s[HD / 4];
    __shared__ float ghs[G3];
    int bid = blockIdx.x;
    int dir = bid >> 2, b = bid & 3;
    const float* Wh = dir ? Wh_b : Wh_f;
    const float* bh = dir ? bh_b : bh_f;
    int tid = threadIdx.x;               // 384

    float w[HD];
#pragma unroll
    for (int k = 0; k < HD; k++) w[k] = Wh[k * G3 + tid];
    float bhj = bh[tid];
    float hreg = 0.f;
    if (tid < HD) ((float*)h4s)[tid] = 0.f;
    __syncthreads();

    for (int step = 0; step < TT; step++) {
        int t = dir ? (TT - 1 - step) : step;
        const float* gxp = &g_gx[((dir * NB + b) * TT + t) * G3];
        float gx0 = 0.f, gx1 = 0.f, gx2 = 0.f;
        int mtok = 0;
        if (tid < HD) {                  // issued early; latency overlapped by acc loop
            gx0 = gxp[tid];
            gx1 = gxp[tid + HD];
            gx2 = gxp[tid + 2 * HD];
            mtok = q[b * TT + t];
        }
        float acc = bhj;
#pragma unroll
        for (int k4 = 0; k4 < HD / 4; k4++) {
            float4 h4 = h4s[k4];
            acc += h4.x * w[4 * k4] + h4.y * w[4 * k4 + 1]
                 + h4.z * w[4 * k4 + 2] + h4.w * w[4 * k4 + 3];
        }
        ghs[tid] = acc;
        __syncthreads();
        if (tid < HD) {
            float r  = sigmoidf_(gx0 + acc);              // acc == gh_r for tid<128
            float z  = sigmoidf_(gx1 + ghs[tid + HD]);
            float nn = tanhf(gx2 + r * ghs[tid + 2 * HD]);
            float hnew = (1.f - z) * nn + z * hreg;
            hreg = mtok ? hnew : hreg;
            ((float*)h4s)[tid] = hreg;
        }
        __syncthreads();
    }
    if (tid < HD) g_qemb[b * HID + dir * HD + tid] = hreg;
}

// ---------------- q_g = q_emb @ W_hg + b_hg (k-split, 8 blocks) --------------
__global__ void k_qg(const float* __restrict__ W_hg, const float* __restrict__ b_hg) {
    int c = blockIdx.x;                  // k-chunk 0..7
    int tid = threadIdx.x;               // 256
    int b = tid >> 6, g = tid & 63;
    float acc = 0.f;
#pragma unroll
    for (int kk = 0; kk < 32; kk++) {
        int k = c * 32 + kk;
        acc += g_qemb[b * HID + k] * W_hg[k * GDIM + g];
    }
    if (c == 0) acc += b_hg[g];
    atomicAdd(&g_qg[tid], acc);
}

// ---------------- attention over descriptions -> node features ---------------
__global__ void k_nodefeat(const int* __restrict__ node_descs,
                           const float* __restrict__ emb_desc) {
    __shared__ float ds[DESCL * DP];
    __shared__ float qgs[NB * GDIM];
    __shared__ float sc[NB * DESCL];
    __shared__ float at[NB * DESCL];
    int n = blockIdx.x;
    int tid = threadIdx.x;               // 256
    qgs[tid] = g_qg[tid];
    {
        int l = tid >> 4, r = tid & 15;
        int idx = node_descs[n * DESCL + l];
        float4 v = ((const float4*)emb_desc)[(long)idx * (GDIM / 4) + r];
        ds[l * DP + r * 4 + 0] = v.x;
        ds[l * DP + r * 4 + 1] = v.y;
        ds[l * DP + r * 4 + 2] = v.z;
        ds[l * DP + r * 4 + 3] = v.w;
    }
    __syncthreads();
    if (tid < NB * DESCL) {
        int b = tid >> 4, l = tid & 15;
        float s = 0.f;
#pragma unroll 8
        for (int g = 0; g < GDIM; g++) s += ds[l * DP + g] * qgs[b * GDIM + g];
        sc[tid] = s;
    }
    __syncthreads();
    if (tid < NB) {
        float m = -1e30f;
        for (int l = 0; l < DESCL; l++) m = fmaxf(m, sc[tid * DESCL + l]);
        float su = 0.f;
        for (int l = 0; l < DESCL; l++) { float e = __expf(sc[tid * DESCL + l] - m); at[tid * DESCL + l] = e; su += e; }
        float inv = 1.f / su;
        for (int l = 0; l < DESCL; l++) at[tid * DESCL + l] *= inv;
    }
    __syncthreads();
    int b = tid >> 6, g = tid & 63;
    float o = 0.f;
#pragma unroll
    for (int l = 0; l < DESCL; l++) o += at[b * DESCL + l] * ds[l * DP + g];
    g_nf[n * (NB * GDIM) + tid] = o;
}

// ---------------- CSR build: histogram, scan, bucket -------------------------
__global__ void k_hist(const int* __restrict__ edst) {
    int i = blockIdx.x * blockDim.x + threadIdx.x;
    if (i < NEDGES) atomicAdd(&g_counts[edst[i]], 1);
}

__global__ void k_scan() {
    __shared__ int wsum[32];
    __shared__ int carry_s;
    int tid = threadIdx.x, lane = tid & 31, wid = tid >> 5;
    if (tid == 0) carry_s = 0;
    __syncthreads();
    int nchunk = (NNODES + 1023) / 1024;
    for (int c = 0; c < nchunk; c++) {
        int i = c * 1024 + tid;
        int v = (i < NNODES) ? g_counts[i] : 0;
        int x = v;
#pragma unroll
        for (int o = 1; o < 32; o <<= 1) { int y = __shfl_up_sync(~0u, x, o); if (lane >= o) x += y; }
        if (lane == 31) wsum[wid] = x;
        __syncthreads();
        if (wid == 0) {
            int s = wsum[lane];
#pragma unroll
            for (int o = 1; o < 32; o <<= 1) { int y = __shfl_up_sync(~0u, s, o); if (lane >= o) s += y; }
            wsum[lane] = s;
        }
        __syncthreads();
        int incl = x + (wid > 0 ? wsum[wid - 1] : 0);
        int total = wsum[31];
        int base = carry_s;
        if (i < NNODES) { int e = base + incl - v; g_offsets[i] = e; g_cursor[i] = e; }
        __syncthreads();
        if (tid == 0) carry_s = base + total;
        __syncthreads();
    }
    if (tid == 0) g_offsets[NNODES] = carry_s;
}

__global__ void k_bucket(const int* __restrict__ esrc, const int* __restrict__ edst,
                         const int* __restrict__ etype, const float* __restrict__ w_comp) {
    int i = blockIdx.x * blockDim.x + threadIdx.x;
    if (i < NEDGES) {
        int d = edst[i];
        int pos = atomicAdd(&g_cursor[d], 1);
        g_ssrc[pos] = esrc[i];
        g_sw[pos]   = w_comp[etype[i]];
    }
}

// ---------------- fused: gather + basis transform + relu + score -------------
// Block covers 16 nodes (64 rows of [n][b]). Gather phase: 16 threads/node
// accumulate the weighted sum of 1KB src rows into registers -> smem ar.
// Transform: thread (rg,jq) computes 4 rows x 4 cols with float4 LDS
// (16x fewer warp-LDS than scalar). Score (dot with q_g) folded in via
// 16-lane shuffle reduce -> g_s2.
__global__ void __launch_bounds__(256) k_gts(const float* __restrict__ bases,
                                             const float* __restrict__ rgcn_bias) {
    __shared__ float ar[64 * 64];        // 16 KB: 64 rows ([n_local][b]) x 64
    __shared__ float B0s[GDIM * GDIM];   // 16 KB
    __shared__ float qgs[NB * GDIM];     // 1 KB
    int tid = threadIdx.x;
    int n0 = blockIdx.x * 16;

    for (int i = tid; i < GDIM * GDIM; i += 256) B0s[i] = bases[i];
    qgs[tid] = g_qg[tid];

    // ---- gather ----
    {
        int nl = tid >> 4, q = tid & 15;
        int n = n0 + nl;
        int beg = g_offsets[n], end = g_offsets[n + 1];
        float4 a0 = make_float4(0, 0, 0, 0), a1 = a0, a2 = a0, a3 = a0;
        const float4* nf4 = (const float4*)g_nf;
        int e = beg;
        for (; e + 1 < end; e += 2) {
            int   s0 = g_ssrc[e];     float w0 = g_sw[e];
            int   s1 = g_ssrc[e + 1]; float w1 = g_sw[e + 1];
            const float4* r0p = nf4 + (long)s0 * 64;
            const float4* r1p = nf4 + (long)s1 * 64;
            float4 u0 = r0p[q], u1 = r0p[q + 16], u2 = r0p[q + 32], u3 = r0p[q + 48];
            float4 v0 = r1p[q], v1 = r1p[q + 16], v2 = r1p[q + 32], v3 = r1p[q + 48];
            a0.x += w0 * u0.x + w1 * v0.x; a0.y += w0 * u0.y + w1 * v0.y;
            a0.z += w0 * u0.z + w1 * v0.z; a0.w += w0 * u0.w + w1 * v0.w;
            a1.x += w0 * u1.x + w1 * v1.x; a1.y += w0 * u1.y + w1 * v1.y;
            a1.z += w0 * u1.z + w1 * v1.z; a1.w += w0 * u1.w + w1 * v1.w;
            a2.x += w0 * u2.x + w1 * v2.x; a2.y += w0 * u2.y + w1 * v2.y;
            a2.z += w0 * u2.z + w1 * v2.z; a2.w += w0 * u2.w + w1 * v2.w;
            a3.x += w0 * u3.x + w1 * v3.x; a3.y += w0 * u3.y + w1 * v3.y;
            a3.z += w0 * u3.z + w1 * v3.z; a3.w += w0 * u3.w + w1 * v3.w;
        }
        if (e < end) {
            int s0 = g_ssrc[e]; float w0 = g_sw[e];
            const float4* r0p = nf4 + (long)s0 * 64;
            float4 u0 = r0p[q], u1 = r0p[q + 16], u2 = r0p[q + 32], u3 = r0p[q + 48];
            a0.x += w0 * u0.x; a0.y += w0 * u0.y; a0.z += w0 * u0.z; a0.w += w0 * u0.w;
            a1.x += w0 * u1.x; a1.y += w0 * u1.y; a1.z += w0 * u1.z; a1.w += w0 * u1.w;
            a2.x += w0 * u2.x; a2.y += w0 * u2.y; a2.z += w0 * u2.z; a2.w += w0 * u2.w;
            a3.x += w0 * u3.x; a3.y += w0 * u3.y; a3.z += w0 * u3.z; a3.w += w0 * u3.w;
        }
        // float4 slot i*16+q of node row == (b=i, g4=q); ar row = nl*4 + b
        ((float4*)ar)[(nl * 4 + 0) * 16 + q] = a0;
        ((float4*)ar)[(nl * 4 + 1) * 16 + q] = a1;
        ((float4*)ar)[(nl * 4 + 2) * 16 + q] = a2;
        ((float4*)ar)[(nl * 4 + 3) * 16 + q] = a3;
    }
    __syncthreads();

    // ---- transform: 4 rows x 4 cols per thread ----
    int rg = tid >> 4, jq = tid & 15;
    float4 bias4 = ((const float4*)rgcn_bias)[jq];
    float4 acc0 = bias4, acc1 = bias4, acc2 = bias4, acc3 = bias4;
#pragma unroll 4
    for (int kk = 0; kk < GDIM; kk += 4) {
        float4 ar0 = ((float4*)ar)[(rg * 4 + 0) * 16 + (kk >> 2)];
        float4 ar1 = ((float4*)ar)[(rg * 4 + 1) * 16 + (kk >> 2)];
        float4 ar2 = ((float4*)ar)[(rg * 4 + 2) * 16 + (kk >> 2)];
        float4 ar3 = ((float4*)ar)[(rg * 4 + 3) * 16 + (kk >> 2)];
        float4 b0 = ((float4*)B0s)[(kk + 0) * 16 + jq];
        float4 b1 = ((float4*)B0s)[(kk + 1) * 16 + jq];
        float4 b2 = ((float4*)B0s)[(kk + 2) * 16 + jq];
        float4 b3 = ((float4*)B0s)[(kk + 3) * 16 + jq];
        acc0.x += ar0.x * b0.x + ar0.y * b1.x + ar0.z * b2.x + ar0.w * b3.x;
        acc0.y += ar0.x * b0.y + ar0.y * b1.y + ar0.z * b2.y + ar0.w * b3.y;
        acc0.z += ar0.x * b0.z + ar0.y * b1.z + ar0.z * b2.z + ar0.w * b3.z;
        acc0.w += ar0.x * b0.w + ar0.y * b1.w + ar0.z * b2.w + ar0.w * b3.w;
        acc1.x += ar1.x * b0.x + ar1.y * b1.x + ar1.z * b2.x + ar1.w * b3.x;
        acc1.y += ar1.x * b0.y + ar1.y * b1.y + ar1.z * b2.y + ar1.w * b3.y;
        acc1.z += ar1.x * b0.z + ar1.y * b1.z + ar1.z * b2.z + ar1.w * b3.z;
        acc1.w += ar1.x * b0.w + ar1.y * b1.w + ar1.z * b2.w + ar1.w * b3.w;
        acc2.x += ar2.x * b0.x + ar2.y * b1.x + ar2.z * b2.x + ar2.w * b3.x;
        acc2.y += ar2.x * b0.y + ar2.y * b1.y + ar2.z * b2.y + ar2.w * b3.y;
        acc2.z += ar2.x * b0.z + ar2.y * b1.z + ar2.z * b2.z + ar2.w * b3.z;
        acc2.w += ar2.x * b0.w + ar2.y * b1.w + ar2.z * b2.w + ar2.w * b3.w;
        acc3.x += ar3.x * b0.x + ar3.y * b1.x + ar3.z * b2.x + ar3.w * b3.x;
        acc3.y += ar3.x * b0.y + ar3.y * b1.y + ar3.z * b2.y + ar3.w * b3.y;
        acc3.z += ar3.x * b0.z + ar3.y * b1.z + ar3.z * b2.z + ar3.w * b3.z;
        acc3.w += ar3.x * b0.w + ar3.y * b1.w + ar3.z * b2.w + ar3.w * b3.w;
    }
    // relu
    acc0.x = fmaxf(acc0.x, 0.f); acc0.y = fmaxf(acc0.y, 0.f); acc0.z = fmaxf(acc0.z, 0.f); acc0.w = fmaxf(acc0.w, 0.f);
    acc1.x = fmaxf(acc1.x, 0.f); acc1.y = fmaxf(acc1.y, 0.f); acc1.z = fmaxf(acc1.z, 0.f); acc1.w = fmaxf(acc1.w, 0.f);
    acc2.x = fmaxf(acc2.x, 0.f); acc2.y = fmaxf(acc2.y, 0.f); acc2.z = fmaxf(acc2.z, 0.f); acc2.w = fmaxf(acc2.w, 0.f);
    acc3.x = fmaxf(acc3.x, 0.f); acc3.y = fmaxf(acc3.y, 0.f); acc3.z = fmaxf(acc3.z, 0.f); acc3.w = fmaxf(acc3.w, 0.f);
    // store nf2
    long r0g = (long)blockIdx.x * 64 + rg * 4;
    ((float4*)g_nf2)[(r0g + 0) * 16 + jq] = acc0;
    ((float4*)g_nf2)[(r0g + 1) * 16 + jq] = acc1;
    ((float4*)g_nf2)[(r0g + 2) * 16 + jq] = acc2;
    ((float4*)g_nf2)[(r0g + 3) * 16 + jq] = acc3;
    // score: row (rg*4 + i) has b=i, n = n0+rg
    float4 q0 = ((float4*)qgs)[0 * 16 + jq];
    float4 q1 = ((float4*)qgs)[1 * 16 + jq];
    float4 q2 = ((float4*)qgs)[2 * 16 + jq];
    float4 q3 = ((float4*)qgs)[3 * 16 + jq];
    float s0 = acc0.x * q0.x + acc0.y * q0.y + acc0.z * q0.z + acc0.w * q0.w;
    float s1 = acc1.x * q1.x + acc1.y * q1.y + acc1.z * q1.z + acc1.w * q1.w;
    float s2 = acc2.x * q2.x + acc2.y * q2.y + acc2.z * q2.z + acc2.w * q2.w;
    float s3 = acc3.x * q3.x + acc3.y * q3.y + acc3.z * q3.z + acc3.w * q3.w;
#pragma unroll
    for (int o = 8; o >= 1; o >>= 1) {
        s0 += __shfl_xor_sync(~0u, s0, o);
        s1 += __shfl_xor_sync(~0u, s1, o);
        s2 += __shfl_xor_sync(~0u, s2, o);
        s3 += __shfl_xor_sync(~0u, s3, o);
    }
    if (jq == 0) {
        int n = n0 + rg;
        g_s2[0 * NNODES + n] = s0;
        g_s2[1 * NNODES + n] = s1;
        g_s2[2 * NNODES + n] = s2;
        g_s2[3 * NNODES + n] = s3;
    }
}

// ---------------- softmax stats over nodes -----------------------------------
__global__ void k_redmax() {
    __shared__ float sh[1024];
    int b = blockIdx.x, tid = threadIdx.x;
    float m = -1e30f;
    for (int n = tid; n < NNODES; n += 1024) m = fmaxf(m, g_s2[b * NNODES + n]);
    sh[tid] = m; __syncthreads();
    for (int o = 512; o > 0; o >>= 1) { if (tid < o) sh[tid] = fmaxf(sh[tid], sh[tid + o]); __syncthreads(); }
    float mx = sh[0]; __syncthreads();
    float su = 0.f;
    for (int n = tid; n < NNODES; n += 1024) su += __expf(g_s2[b * NNODES + n] - mx);
    sh[tid] = su; __syncthreads();
    for (int o = 512; o > 0; o >>= 1) { if (tid < o) sh[tid] += sh[tid + o]; __syncthreads(); }
    if (tid == 0) { g_mx[b] = mx; g_sumz[b] = sh[0]; }
    if (tid < GDIM) g_nagg[b * GDIM + tid] = 0.f;
}

// ---------------- pooling (prob computed on the fly) -------------------------
__global__ void k_pool() {
    __shared__ float sh[4][64];
    int b = blockIdx.x >> 5, c = blockIdx.x & 31;
    int tid = threadIdx.x, g = tid & 63, r = tid >> 6;
    float mx = g_mx[b], inv = 1.f / g_sumz[b];
    int n0 = c * 625, n1 = n0 + 625;
    float acc = 0.f;
    for (int n = n0 + r; n < n1; n += 4) {
        float p = __expf(g_s2[b * NNODES + n] - mx) * inv;
        acc += p * g_nf2[(long)n * 256 + b * 64 + g];
    }
    sh[r][g] = acc;
    __syncthreads();
    if (tid < 64) {
        float tot = sh[0][tid] + sh[1][tid] + sh[2][tid] + sh[3][tid];
        atomicAdd(&g_nagg[b * 64 + tid], tot);
    }
}

// ---------------- classifier -------------------------------------------------
__global__ void k_fc1(const float* __restrict__ W1, const float* __restrict__ b1) {
    __shared__ float fs[NB * 320];
    int tid = threadIdx.x;               // 256
    for (int i = tid; i < NB * 320; i += 256) {
        int b = i / 320, kk = i % 320;
        fs[i] = (kk < 64) ? g_nagg[b * 64 + kk] : g_qemb[b * 256 + (kk - 64)];
    }
    __syncthreads();
    int o = blockIdx.x * 256 + tid;      // 4096
    int b = o >> 10, j = o & 1023;
    float acc = b1[j];
#pragma unroll 8
    for (int kk = 0; kk < 320; kk++) acc += fs[b * 320 + kk] * W1[kk * 1024 + j];
    g_hidden[o] = fmaxf(acc, 0.f);
}

__global__ void k_fc2(const float* __restrict__ W2, const float* __restrict__ b2,
                      float* __restrict__ out) {
    __shared__ float hs[NB * 1024];
    int tid = threadIdx.x;               // 256
    for (int i = tid; i < NB * 1024; i += 256) hs[i] = g_hidden[i];
    __syncthreads();
    int o = blockIdx.x * 256 + tid;
    if (o < NB * NCLASS) {
        int b = o / NCLASS, j = o % NCLASS;
        float acc = b2[j];
#pragma unroll 8
        for (int kk = 0; kk < 1024; kk++) acc += hs[b * 1024 + kk] * W2[kk * NCLASS + j];
        out[o] = acc;
    }
}

// ---------------- launch -----------------------------------------------------
extern "C" void kernel_launch(void* const* d_in, const int* in_sizes, int n_in,
                              void* d_out, int out_size) {
    const int*   questions  = (const int*)  d_in[0];
    const int*   node_descs = (const int*)  d_in[1];
    const int*   edge_src   = (const int*)  d_in[2];
    const int*   edge_dst   = (const int*)  d_in[3];
    const int*   edge_type  = (const int*)  d_in[4];
    const float* emb_word   = (const float*)d_in[5];
    const float* emb_desc   = (const float*)d_in[6];
    const float* Wx_f       = (const float*)d_in[7];
    const float* Wh_f       = (const float*)d_in[8];
    const float* bx_f       = (const float*)d_in[9];
    const float* bh_f       = (const float*)d_in[10];
    const float* Wx_b       = (const float*)d_in[11];
    const float* Wh_b       = (const float*)d_in[12];
    const float* bx_b       = (const float*)d_in[13];
    const float* bh_b       = (const float*)d_in[14];
    const float* W_hg       = (const float*)d_in[15];
    const float* b_hg       = (const float*)d_in[16];
    const float* bases      = (const float*)d_in[17];
    const float* w_comp     = (const float*)d_in[18];
    const float* rgcn_bias  = (const float*)d_in[19];
    const float* W1         = (const float*)d_in[20];
    const float* b1         = (const float*)d_in[21];
    const float* W2         = (const float*)d_in[22];
    const float* b2         = (const float*)d_in[23];
    float* out = (float*)d_out;

    k_zero<<<(NNODES + 256) / 256, 256>>>();
    k_gx<<<32, 384>>>(questions, emb_word, Wx_f, bx_f, Wx_b, bx_b);
    k_gru<<<8, 384>>>(Wh_f, bh_f, Wh_b, bh_b, questions);
    k_qg<<<8, 256>>>(W_hg, b_hg);
    k_hist<<<(NEDGES + 255) / 256, 256>>>(edge_dst);
    k_scan<<<1, 1024>>>();
    k_bucket<<<(NEDGES + 255) / 256, 256>>>(edge_src, edge_dst, edge_type, w_comp);
    k_nodefeat<<<NNODES, 256>>>(node_descs, emb_desc);
    k_gts<<<NNODES / 16, 256>>>(bases, rgcn_bias);
    k_redmax<<<NB, 1024>>>();
    k_pool<<<NB * 32, 256>>>();
    k_fc1<<<16, 256>>>(W1, b1);
    k_fc2<<<(NB * NCLASS + 255) / 256, 256>>>(W2, b2, out);
}

// round 3
// speedup vs baseline: 2.3539x; 1.5400x over previous
#include <cuda_runtime.h>
#include <cuda_fp16.h>
#include <cuda_bf16.h>

#define NB      4
#define TT      32
#define DW      300
#define HD      128     // per-direction hidden
#define G3      384     // 3*HD
#define HID     256     // DIM_HIDDEN
#define GDIM    64
#define DESCL   16
#define NNODES  20000
#define NEDGES  320000
#define NCLASS  2000
#define DP      68      // padded desc row in smem
#define TGRID   148     // tail grid (<= SM count, all co-resident)
#define CHUNK   136     // ceil(NNODES/TGRID)

// ---------------- scratch (device globals; zero-init at load) ---------------
// g_counts, g_qg, g_flag are zero at load and re-zeroed by the tail kernel of
// each call for the next call (deterministic invariant maintenance).
__device__ float g_gxa[2 * NB * TT * G3];     // input gates, k-half 0
__device__ float g_gxb[2 * NB * TT * G3];     // input gates, k-half 1
__device__ float g_qemb[NB * HID];
__device__ float g_qg[NB * GDIM];             // accum: maintained zero
__device__ __half g_nfh[(size_t)NNODES * NB * GDIM];  // node feats (fp16)
__device__ float g_nf2[(size_t)NNODES * NB * GDIM];   // post-RGCN (fp32)
__device__ int   g_counts[NNODES];            // maintained zero
__device__ int   g_offsets[NNODES + 1];
__device__ int   g_cursor[NNODES];
__device__ int   g_ssrc[NEDGES];
__device__ float g_sw[NEDGES];
__device__ float g_s2[NB * NNODES];
__device__ float g_pmax[TGRID * NB];
__device__ float g_psum[TGRID * NB];
__device__ float g_nagg[NB * GDIM];
__device__ float g_hidden[NB * 1024];
__device__ volatile int g_flag;               // maintained zero
__device__ volatile unsigned g_barcnt;        // returns to 0 every call
__device__ volatile unsigned g_barsense;      // even #barriers -> returns to 0

__device__ __forceinline__ float sigmoidf_(float x) { return 1.f / (1.f + __expf(-x)); }

// =====================================================================
// Launch A: gx (64 blocks, k-split by 2) + edge-dst histogram (834 blocks)
// =====================================================================
__global__ void __launch_bounds__(384) k_front(
    const int* __restrict__ q, const float* __restrict__ emb_word,
    const float* __restrict__ Wx_f, const float* __restrict__ bx_f,
    const float* __restrict__ Wx_b, const float* __restrict__ bx_b,
    const int* __restrict__ edst) {
    int bid = blockIdx.x, tid = threadIdx.x;
    if (bid < 64) {
        // gx: bid = half(1) dir(1) b(2) tq(2)
        int half = bid >> 5, dir = (bid >> 4) & 1, b = (bid >> 2) & 3, tq = bid & 3;
        const float* Wx = dir ? Wx_b : Wx_f;
        const float* bx = dir ? bx_b : bx_f;
        int k0 = half * 150;
        __shared__ float xs[8 * 150];
        for (int i = tid; i < 8 * 150; i += 384) {
            int t = i / 150, k = i % 150;
            int tok = q[b * TT + tq * 8 + t];
            xs[i] = emb_word[(long)tok * DW + k0 + k];
        }
        __syncthreads();
        float acc[8];
        float bj = half ? 0.f : bx[tid];
#pragma unroll
        for (int t = 0; t < 8; t++) acc[t] = bj;
        for (int k = 0; k < 150; k++) {
            float w = Wx[(long)(k0 + k) * G3 + tid];
#pragma unroll
            for (int t = 0; t < 8; t++) acc[t] += xs[t * 150 + k] * w;
        }
        float* dst = half ? g_gxb : g_gxa;
#pragma unroll
        for (int t = 0; t < 8; t++)
            dst[((dir * NB + b) * TT + tq * 8 + t) * G3 + tid] = acc[t];
    } else {
        int i = (bid - 64) * 384 + tid;
        if (i < NEDGES) atomicAdd(&g_counts[edst[i]], 1);
    }
}

// =====================================================================
// Launch B: GRU recurrence (Wh register-resident) + fused q_g partial GEMV
// 8 blocks = (dir, b). g_qg pre-zeroed; bias b_hg added by consumers.
// =====================================================================
__global__ void __launch_bounds__(384, 1)
k_gruq(const float* __restrict__ Wh_f, const float* __restrict__ bh_f,
       const float* __restrict__ Wh_b, const float* __restrict__ bh_b,
       const int* __restrict__ q, const float* __restrict__ W_hg) {
    __shared__ float4 h4s[HD / 4];
    __shared__ float ghs[G3];
    int bid = blockIdx.x;
    int dir = bid >> 2, b = bid & 3;
    const float* Wh = dir ? Wh_b : Wh_f;
    const float* bh = dir ? bh_b : bh_f;
    int tid = threadIdx.x;               // 384

    float w[HD];
#pragma unroll
    for (int k = 0; k < HD; k++) w[k] = Wh[k * G3 + tid];
    float bhj = bh[tid];
    float hreg = 0.f;
    if (tid < HD) ((float*)h4s)[tid] = 0.f;
    __syncthreads();

    for (int step = 0; step < TT; step++) {
        int t = dir ? (TT - 1 - step) : step;
        const float* gA = &g_gxa[((dir * NB + b) * TT + t) * G3];
        const float* gB = &g_gxb[((dir * NB + b) * TT + t) * G3];
        float gx0 = 0.f, gx1 = 0.f, gx2 = 0.f;
        int mtok = 0;
        if (tid < HD) {
            gx0 = gA[tid] + gB[tid];
            gx1 = gA[tid + HD] + gB[tid + HD];
            gx2 = gA[tid + 2 * HD] + gB[tid + 2 * HD];
            mtok = q[b * TT + t];
        }
        float acc = bhj;
#pragma unroll
        for (int k4 = 0; k4 < HD / 4; k4++) {
            float4 h4 = h4s[k4];
            acc += h4.x * w[4 * k4] + h4.y * w[4 * k4 + 1]
                 + h4.z * w[4 * k4 + 2] + h4.w * w[4 * k4 + 3];
        }
        ghs[tid] = acc;
        __syncthreads();
        if (tid < HD) {
            float r  = sigmoidf_(gx0 + acc);
            float z  = sigmoidf_(gx1 + ghs[tid + HD]);
            float nn = tanhf(gx2 + r * ghs[tid + 2 * HD]);
            float hnew = (1.f - z) * nn + z * hreg;
            hreg = mtok ? hnew : hreg;
            ((float*)h4s)[tid] = hreg;
        }
        __syncthreads();
    }
    if (tid < HD) g_qemb[b * HID + dir * HD + tid] = hreg;
    // partial q_g: this block's 128 k-dims of qemb contract with W_hg
    if (tid < GDIM) {
        const float* hh = (const float*)h4s;
        float acc = 0.f;
#pragma unroll 8
        for (int k = 0; k < HD; k++)
            acc += hh[k] * W_hg[(dir * HD + k) * GDIM + tid];
        atomicAdd(&g_qg[b * GDIM + tid], acc);
    }
}

// =====================================================================
// Launch C (blockDim 1024): block 0 = CSR scan (+flag release);
// blocks 1..5000 = nodefeat (4 nodes each, fp16 out);
// blocks 5001..5313 = bucket (spin on flag; scheduled last -> no real spin)
// =====================================================================
__global__ void __launch_bounds__(1024) k_mid(
    const int* __restrict__ node_descs, const float* __restrict__ emb_desc,
    const float* __restrict__ b_hg,
    const int* __restrict__ esrc, const int* __restrict__ edst,
    const int* __restrict__ etype, const float* __restrict__ w_comp) {
    int blk = blockIdx.x, tid = threadIdx.x;
    __shared__ float ds[4][DESCL * DP];
    __shared__ float qgs[NB * GDIM];
    __shared__ float sc[4][NB * DESCL];
    __shared__ float at[4][NB * DESCL];
    __shared__ int wsum[32];
    __shared__ int carry_s;

    if (blk == 0) {
        // ---- exclusive scan of g_counts -> g_offsets, g_cursor ----
        int lane = tid & 31, wid = tid >> 5;
        if (tid == 0) carry_s = 0;
        __syncthreads();
        int nchunk = (NNODES + 1023) / 1024;
        for (int c = 0; c < nchunk; c++) {
            int i = c * 1024 + tid;
            int v = (i < NNODES) ? g_counts[i] : 0;
            int x = v;
#pragma unroll
            for (int o = 1; o < 32; o <<= 1) { int y = __shfl_up_sync(~0u, x, o); if (lane >= o) x += y; }
            if (lane == 31) wsum[wid] = x;
            __syncthreads();
            if (wid == 0) {
                int s = wsum[lane];
#pragma unroll
                for (int o = 1; o < 32; o <<= 1) { int y = __shfl_up_sync(~0u, s, o); if (lane >= o) s += y; }
                wsum[lane] = s;
            }
            __syncthreads();
            int incl = x + (wid > 0 ? wsum[wid - 1] : 0);
            int total = wsum[31];
            int base = carry_s;
            if (i < NNODES) { int e = base + incl - v; g_offsets[i] = e; g_cursor[i] = e; }
            __syncthreads();
            if (tid == 0) carry_s = base + total;
            __syncthreads();
        }
        if (tid == 0) g_offsets[NNODES] = carry_s;
        __syncthreads();
        if (tid == 0) { __threadfence(); g_flag = 1; }
    } else if (blk <= NNODES / 4) {
        // ---- nodefeat: 4 nodes per block ----
        int sub = tid >> 8, t = tid & 255;
        int n = (blk - 1) * 4 + sub;
        if (sub == 0) qgs[t] = g_qg[t] + b_hg[t & 63];
        {
            int l = t >> 4, r = t & 15;
            int idx = node_descs[n * DESCL + l];
            float4 v = ((const float4*)emb_desc)[(long)idx * (GDIM / 4) + r];
            ds[sub][l * DP + r * 4 + 0] = v.x;
            ds[sub][l * DP + r * 4 + 1] = v.y;
            ds[sub][l * DP + r * 4 + 2] = v.z;
            ds[sub][l * DP + r * 4 + 3] = v.w;
        }
        __syncthreads();
        if (t < NB * DESCL) {
            int b = t >> 4, l = t & 15;
            float s = 0.f;
#pragma unroll 8
            for (int g = 0; g < GDIM; g++) s += ds[sub][l * DP + g] * qgs[b * GDIM + g];
            sc[sub][t] = s;
        }
        __syncthreads();
        if (t < NB) {
            float m = -1e30f;
            for (int l = 0; l < DESCL; l++) m = fmaxf(m, sc[sub][t * DESCL + l]);
            float su = 0.f;
            for (int l = 0; l < DESCL; l++) { float e = __expf(sc[sub][t * DESCL + l] - m); at[sub][t * DESCL + l] = e; su += e; }
            float inv = 1.f / su;
            for (int l = 0; l < DESCL; l++) at[sub][t * DESCL + l] *= inv;
        }
        __syncthreads();
        int b = t >> 6, g = t & 63;
        float o = 0.f;
#pragma unroll
        for (int l = 0; l < DESCL; l++) o += at[sub][b * DESCL + l] * ds[sub][l * DP + g];
        g_nfh[(size_t)n * 256 + t] = __float2half(o);
    } else {
        // ---- bucket: wait for scan, then place edges ----
        if (tid == 0) { while (g_flag == 0) {} __threadfence(); }
        __syncthreads();
        int i = (blk - (NNODES / 4 + 1)) * 1024 + tid;
        if (i < NEDGES) {
            int d = edst[i];
            int pos = atomicAdd(&g_cursor[d], 1);
            g_ssrc[pos] = esrc[i];
            g_sw[pos]   = w_comp[etype[i]];
        }
    }
}

// =====================================================================
// Launch D: fused gather (fp16 src rows) + basis transform + relu + score
// Block = 16 nodes. 16 threads/node accumulate fp32 from half2 rows.
// =====================================================================
__global__ void __launch_bounds__(256) k_gts(const float* __restrict__ bases,
                                             const float* __restrict__ rgcn_bias,
                                             const float* __restrict__ b_hg) {
    __shared__ float ar[64 * 64];        // 16 KB
    __shared__ float B0s[GDIM * GDIM];   // 16 KB
    __shared__ float qgs[NB * GDIM];
    int tid = threadIdx.x;
    int n0 = blockIdx.x * 16;

    for (int i = tid; i < GDIM * GDIM; i += 256) B0s[i] = bases[i];
    qgs[tid] = g_qg[tid] + b_hg[tid & 63];

    // ---- gather (half storage, fp32 accum) ----
    {
        int nl = tid >> 4, q = tid & 15;
        int n = n0 + nl;
        int beg = g_offsets[n], end = g_offsets[n + 1];
        float aa[8], ab[8];
#pragma unroll
        for (int j = 0; j < 8; j++) { aa[j] = 0.f; ab[j] = 0.f; }
        const uint4* nf4 = (const uint4*)g_nfh;   // 32 uint4 per node row (512B)
#define ACC8(Uv, acc, wv) { \
        const __half2* hp_ = (const __half2*)&(Uv); \
        float2 f0_ = __half22float2(hp_[0]); float2 f1_ = __half22float2(hp_[1]); \
        float2 f2_ = __half22float2(hp_[2]); float2 f3_ = __half22float2(hp_[3]); \
        acc[0] += (wv) * f0_.x; acc[1] += (wv) * f0_.y; \
        acc[2] += (wv) * f1_.x; acc[3] += (wv) * f1_.y; \
        acc[4] += (wv) * f2_.x; acc[5] += (wv) * f2_.y; \
        acc[6] += (wv) * f3_.x; acc[7] += (wv) * f3_.y; }
        int e = beg;
        for (; e + 1 < end; e += 2) {
            int   s0 = g_ssrc[e];     float w0 = g_sw[e];
            int   s1 = g_ssrc[e + 1]; float w1 = g_sw[e + 1];
            uint4 U0 = nf4[(long)s0 * 32 + q];
            uint4 V0 = nf4[(long)s0 * 32 + q + 16];
            uint4 U1 = nf4[(long)s1 * 32 + q];
            uint4 V1 = nf4[(long)s1 * 32 + q + 16];
            ACC8(U0, aa, w0); ACC8(V0, ab, w0);
            ACC8(U1, aa, w1); ACC8(V1, ab, w1);
        }
        if (e < end) {
            int s0 = g_ssrc[e]; float w0 = g_sw[e];
            uint4 U0 = nf4[(long)s0 * 32 + q];
            uint4 V0 = nf4[(long)s0 * 32 + q + 16];
            ACC8(U0, aa, w0); ACC8(V0, ab, w0);
        }
#undef ACC8
        // thread q's first uint4 covers h=[8q,8q+8): b=q>>3, g0=(q&7)*8;
        // second covers b+2. ar rows = nl*4 + b.
        int ba = q >> 3, g0 = (q & 7) * 8;
        float4* pa = (float4*)&ar[(nl * 4 + ba) * 64 + g0];
        pa[0] = make_float4(aa[0], aa[1], aa[2], aa[3]);
        pa[1] = make_float4(aa[4], aa[5], aa[6], aa[7]);
        float4* pb = (float4*)&ar[(nl * 4 + 2 + ba) * 64 + g0];
        pb[0] = make_float4(ab[0], ab[1], ab[2], ab[3]);
        pb[1] = make_float4(ab[4], ab[5], ab[6], ab[7]);
    }
    __syncthreads();

    // ---- transform: 4 rows x 4 cols per thread ----
    int rg = tid >> 4, jq = tid & 15;
    float4 bias4 = ((const float4*)rgcn_bias)[jq];
    float4 acc0 = bias4, acc1 = bias4, acc2 = bias4, acc3 = bias4;
#pragma unroll 4
    for (int kk = 0; kk < GDIM; kk += 4) {
        float4 ar0 = ((float4*)ar)[(rg * 4 + 0) * 16 + (kk >> 2)];
        float4 ar1 = ((float4*)ar)[(rg * 4 + 1) * 16 + (kk >> 2)];
        float4 ar2 = ((float4*)ar)[(rg * 4 + 2) * 16 + (kk >> 2)];
        float4 ar3 = ((float4*)ar)[(rg * 4 + 3) * 16 + (kk >> 2)];
        float4 b0 = ((float4*)B0s)[(kk + 0) * 16 + jq];
        float4 b1 = ((float4*)B0s)[(kk + 1) * 16 + jq];
        float4 b2 = ((float4*)B0s)[(kk + 2) * 16 + jq];
        float4 b3 = ((float4*)B0s)[(kk + 3) * 16 + jq];
        acc0.x += ar0.x * b0.x + ar0.y * b1.x + ar0.z * b2.x + ar0.w * b3.x;
        acc0.y += ar0.x * b0.y + ar0.y * b1.y + ar0.z * b2.y + ar0.w * b3.y;
        acc0.z += ar0.x * b0.z + ar0.y * b1.z + ar0.z * b2.z + ar0.w * b3.z;
        acc0.w += ar0.x * b0.w + ar0.y * b1.w + ar0.z * b2.w + ar0.w * b3.w;
        acc1.x += ar1.x * b0.x + ar1.y * b1.x + ar1.z * b2.x + ar1.w * b3.x;
        acc1.y += ar1.x * b0.y + ar1.y * b1.y + ar1.z * b2.y + ar1.w * b3.y;
        acc1.z += ar1.x * b0.z + ar1.y * b1.z + ar1.z * b2.z + ar1.w * b3.z;
        acc1.w += ar1.x * b0.w + ar1.y * b1.w + ar1.z * b2.w + ar1.w * b3.w;
        acc2.x += ar2.x * b0.x + ar2.y * b1.x + ar2.z * b2.x + ar2.w * b3.x;
        acc2.y += ar2.x * b0.y + ar2.y * b1.y + ar2.z * b2.y + ar2.w * b3.y;
        acc2.z += ar2.x * b0.z + ar2.y * b1.z + ar2.z * b2.z + ar2.w * b3.z;
        acc2.w += ar2.x * b0.w + ar2.y * b1.w + ar2.z * b2.w + ar2.w * b3.w;
        acc3.x += ar3.x * b0.x + ar3.y * b1.x + ar3.z * b2.x + ar3.w * b3.x;
        acc3.y += ar3.x * b0.y + ar3.y * b1.y + ar3.z * b2.y + ar3.w * b3.y;
        acc3.z += ar3.x * b0.z + ar3.y * b1.z + ar3.z * b2.z + ar3.w * b3.z;
        acc3.w += ar3.x * b0.w + ar3.y * b1.w + ar3.z * b2.w + ar3.w * b3.w;
    }
    acc0.x = fmaxf(acc0.x, 0.f); acc0.y = fmaxf(acc0.y, 0.f); acc0.z = fmaxf(acc0.z, 0.f); acc0.w = fmaxf(acc0.w, 0.f);
    acc1.x = fmaxf(acc1.x, 0.f); acc1.y = fmaxf(acc1.y, 0.f); acc1.z = fmaxf(acc1.z, 0.f); acc1.w = fmaxf(acc1.w, 0.f);
    acc2.x = fmaxf(acc2.x, 0.f); acc2.y = fmaxf(acc2.y, 0.f); acc2.z = fmaxf(acc2.z, 0.f); acc2.w = fmaxf(acc2.w, 0.f);
    acc3.x = fmaxf(acc3.x, 0.f); acc3.y = fmaxf(acc3.y, 0.f); acc3.z = fmaxf(acc3.z, 0.f); acc3.w = fmaxf(acc3.w, 0.f);
    long r0g = (long)blockIdx.x * 64 + rg * 4;
    ((float4*)g_nf2)[(r0g + 0) * 16 + jq] = acc0;
    ((float4*)g_nf2)[(r0g + 1) * 16 + jq] = acc1;
    ((float4*)g_nf2)[(r0g + 2) * 16 + jq] = acc2;
    ((float4*)g_nf2)[(r0g + 3) * 16 + jq] = acc3;
    // score vs q_g
    float4 q0 = ((float4*)qgs)[0 * 16 + jq];
    float4 q1 = ((float4*)qgs)[1 * 16 + jq];
    float4 q2 = ((float4*)qgs)[2 * 16 + jq];
    float4 q3 = ((float4*)qgs)[3 * 16 + jq];
    float s0 = acc0.x * q0.x + acc0.y * q0.y + acc0.z * q0.z + acc0.w * q0.w;
    float s1 = acc1.x * q1.x + acc1.y * q1.y + acc1.z * q1.z + acc1.w * q1.w;
    float s2 = acc2.x * q2.x + acc2.y * q2.y + acc2.z * q2.z + acc2.w * q2.w;
    float s3 = acc3.x * q3.x + acc3.y * q3.y + acc3.z * q3.z + acc3.w * q3.w;
#pragma unroll
    for (int o = 8; o >= 1; o >>= 1) {
        s0 += __shfl_xor_sync(~0u, s0, o);
        s1 += __shfl_xor_sync(~0u, s1, o);
        s2 += __shfl_xor_sync(~0u, s2, o);
        s3 += __shfl_xor_sync(~0u, s3, o);
    }
    if (jq == 0) {
        int n = n0 + rg;
        g_s2[0 * NNODES + n] = s0;
        g_s2[1 * NNODES + n] = s1;
        g_s2[2 * NNODES + n] = s2;
        g_s2[3 * NNODES + n] = s3;
    }
}

// =====================================================================
// Launch E: persistent tail. 148 blocks x 256, 4 grid barriers.
// P0 partial-max  P1 global-max + partial expsum  P2 total sum + pool
// P3 fc1  P4 fc2 + zero-maintenance for next call.
// =====================================================================
__device__ __forceinline__ void gridbar(unsigned target) {
    __syncthreads();
    if (threadIdx.x == 0) {
        __threadfence();
        unsigned old = atomicAdd((unsigned*)&g_barcnt, 1u);
        if (old == gridDim.x - 1u) {
            g_barcnt = 0;
            __threadfence();
            g_barsense = target;
        } else {
            while (g_barsense != target) {}
        }
        __threadfence();
    }
    __syncthreads();
}

__global__ void __launch_bounds__(256) k_tail(
    const float* __restrict__ W1, const float* __restrict__ b1,
    const float* __restrict__ W2, const float* __restrict__ b2,
    float* __restrict__ out) {
    __shared__ float red[256];
    __shared__ float smx[NB], sinv[NB];
    __shared__ float prob[NB * CHUNK];
    __shared__ float fs[NB * 320];
    __shared__ float hs[NB * 1024];
    int blk = blockIdx.x, tid = threadIdx.x;
    int b = tid >> 6, l = tid & 63;
    int n0 = blk * CHUNK;
    int n1 = n0 + CHUNK; if (n1 > NNODES) n1 = NNODES;

    // ---- P0: per-block partial max per b ----
    float m = -1e30f;
    for (int n = n0 + l; n < n1; n += 64) m = fmaxf(m, g_s2[b * NNODES + n]);
    red[tid] = m; __syncthreads();
#pragma unroll
    for (int o = 32; o > 0; o >>= 1) { if (l < o) red[tid] = fmaxf(red[tid], red[tid + o]); __syncthreads(); }
    if (l == 0) g_pmax[blk * NB + b] = red[tid];
    if (blk == 0) g_nagg[tid] = 0.f;
    gridbar(1);

    // ---- P1: global max; partial expsum ----
    float mx = -1e30f;
    for (int i = l; i < TGRID; i += 64) mx = fmaxf(mx, g_pmax[i * NB + b]);
    red[tid] = mx; __syncthreads();
#pragma unroll
    for (int o = 32; o > 0; o >>= 1) { if (l < o) red[tid] = fmaxf(red[tid], red[tid + o]); __syncthreads(); }
    mx = red[tid & ~63];
    __syncthreads();
    float s = 0.f;
    for (int n = n0 + l; n < n1; n += 64) s += __expf(g_s2[b * NNODES + n] - mx);
    red[tid] = s; __syncthreads();
#pragma unroll
    for (int o = 32; o > 0; o >>= 1) { if (l < o) red[tid] += red[tid + o]; __syncthreads(); }
    if (l == 0) g_psum[blk * NB + b] = red[tid];
    gridbar(0);

    // ---- P2: total sum; probs to smem; pooled weighted sum ----
    float su = 0.f;
    for (int i = l; i < TGRID; i += 64) su += g_psum[i * NB + b];
    red[tid] = su; __syncthreads();
#pragma unroll
    for (int o = 32; o > 0; o >>= 1) { if (l < o) red[tid] += red[tid + o]; __syncthreads(); }
    if (l == 0) { smx[b] = mx; sinv[b] = 1.f / red[tid]; }
    __syncthreads();
    int cnt = n1 - n0;
    for (int i = tid; i < NB * CHUNK; i += 256) {
        int bb = i / CHUNK, j = i % CHUNK;
        if (j < cnt) prob[i] = __expf(g_s2[bb * NNODES + n0 + j] - smx[bb]) * sinv[bb];
    }
    __syncthreads();
    float acc = 0.f;
    for (int j = 0; j < cnt; j++)
        acc += prob[b * CHUNK + j] * g_nf2[(long)(n0 + j) * 256 + tid];
    atomicAdd(&g_nagg[tid], acc);
    gridbar(1);

    // ---- P3: fc1 (blocks 0..15) ----
    if (blk < 16) {
        for (int i = tid; i < NB * 320; i += 256) {
            int bq = i / 320, kk = i % 320;
            fs[i] = (kk < 64) ? g_nagg[bq * 64 + kk] : g_qemb[bq * 256 + (kk - 64)];
        }
        __syncthreads();
        int o = blk * 256 + tid;
        int bo = o >> 10, j = o & 1023;
        float a = b1[j];
#pragma unroll 8
        for (int kk = 0; kk < 320; kk++) a += fs[bo * 320 + kk] * W1[kk * 1024 + j];
        g_hidden[o] = fmaxf(a, 0.f);
    }
    gridbar(0);

    // ---- P4: fc2 (blocks 0..31) + zero maintenance (blocks 32..147) ----
    if (blk < 32) {
        for (int i = tid; i < NB * 1024; i += 256) hs[i] = g_hidden[i];
        __syncthreads();
        int o = blk * 256 + tid;
        if (o < NB * NCLASS) {
            int bo = o / NCLASS, j = o % NCLASS;
            float a = b2[j];
#pragma unroll 8
            for (int kk = 0; kk < 1024; kk++) a += hs[bo * 1024 + kk] * W2[kk * NCLASS + j];
            out[o] = a;
        }
    } else {
        int idx = (blk - 32) * 256 + tid;
        if (idx < NNODES) g_counts[idx] = 0;
        else {
            int j = idx - NNODES;
            if (j < NB * GDIM) g_qg[j] = 0.f;
            else if (j == NB * GDIM) g_flag = 0;
        }
    }
}

// ---------------- launch -----------------------------------------------------
extern "C" void kernel_launch(void* const* d_in, const int* in_sizes, int n_in,
                              void* d_out, int out_size) {
    const int*   questions  = (const int*)  d_in[0];
    const int*   node_descs = (const int*)  d_in[1];
    const int*   edge_src   = (const int*)  d_in[2];
    const int*   edge_dst   = (const int*)  d_in[3];
    const int*   edge_type  = (const int*)  d_in[4];
    const float* emb_word   = (const float*)d_in[5];
    const float* emb_desc   = (const float*)d_in[6];
    const float* Wx_f       = (const float*)d_in[7];
    const float* Wh_f       = (const float*)d_in[8];
    const float* bx_f       = (const float*)d_in[9];
    const float* bh_f       = (const float*)d_in[10];
    const float* Wx_b       = (const float*)d_in[11];
    const float* Wh_b       = (const float*)d_in[12];
    const float* bx_b       = (const float*)d_in[13];
    const float* bh_b       = (const float*)d_in[14];
    const float* W_hg       = (const float*)d_in[15];
    const float* b_hg       = (const float*)d_in[16];
    const float* bases      = (const float*)d_in[17];
    const float* w_comp     = (const float*)d_in[18];
    const float* rgcn_bias  = (const float*)d_in[19];
    const float* W1         = (const float*)d_in[20];
    const float* b1         = (const float*)d_in[21];
    const float* W2         = (const float*)d_in[22];
    const float* b2         = (const float*)d_in[23];
    float* out = (float*)d_out;

    const int histBlocks = (NEDGES + 383) / 384;            // 834
    const int bucketBlocks = (NEDGES + 1023) / 1024;        // 313
    k_front<<<64 + histBlocks, 384>>>(questions, emb_word, Wx_f, bx_f, Wx_b, bx_b, edge_dst);
    k_gruq<<<8, 384>>>(Wh_f, bh_f, Wh_b, bh_b, questions, W_hg);
    k_mid<<<1 + NNODES / 4 + bucketBlocks, 1024>>>(node_descs, emb_desc, b_hg,
                                                   edge_src, edge_dst, edge_type, w_comp);
    k_gts<<<NNODES / 16, 256>>>(bases, rgcn_bias, b_hg);
    k_tail<<<TGRID, 256>>>(W1, b1, W2, b2, out);
}